// round 13
// baseline (speedup 1.0000x reference)
#include <cuda_runtime.h>

// ---------------------------------------------------------------------------
// CMIAttentionMatrixForAcrobot, restructured, continuously-pipelined streams:
//   T[j,i]   = sum_n data_q[n,i] * W_lin[j,n]            (splitk -> red.v4 into g_T)
//   k[j,m]   = sum_i data_k[j,i] * W_k[m,i] + b_k[m]     (rowgemv3 -> g_fin0)
//   nq[m,j]  = sum_i W_q[m,i] * T[j,i] + ...             (rowgemv3 -> g_fin1)
//   kmod     = relu6(k^2 + 2k + nq*(1+|k|))              (vsplit prologue)
//   v[j,i]   = sum_m W_q[m,i] * kmod[j,m]                (splitk -> red.v4 into g_v)
//   c[j]     = sum_m b_q[m] * kmod[j,m]                  (epilogue B)
//   out[n,j] = (sum_i data_q[n,i] * v[j,i] + c[j]) / 64  (rowgemv3 -> g_fin2 + epiB)
// rowgemv3: block owns 8 rows, loops 16 column chunks with double-buffered
// cp.async prefetch -> memory requests are continuous (no bulk-sync duty-cycle
// loss) and accumulators persist -> full dot products, no partial slabs.
// splitk: 8-stage barrier-free per-thread cp.async ring (112B/thread in flight).
// 5 launches. g_T/g_v zero-invariant maintained by epilogueB's tail.
// ---------------------------------------------------------------------------

typedef unsigned long long u64;

#define N_DIM 4096
#define JD 6
#define NTHR 256

// splitk: RPS rows x 1024 cols per block
#define RPS_T 64
#define NSPLIT_T 64
#define SPLITK_T_BLOCKS (4 * NSPLIT_T)    // 256
#define RPS_V 32
#define NSPLIT_V 128

// rowgemv3: 8 rows x full 4096 cols per block, 16 chunks of 256 cols
#define CPK 256
#define KS_ITERS (N_DIM / CPK)            // 16
#define RGROWS 8
#define RGX (N_DIM / RGROWS)              // 512 blocks per pass

#define EPIB_BLOCKS 32

// scratch (static device globals; zero-initialized at module load)
__device__ float g_T[JD * N_DIM];
__device__ float g_v[JD * N_DIM];
__device__ float g_kmod[JD * N_DIM];
__device__ float g_fin[3][N_DIM * JD];    // 0: k, 1: nq, 2: dot (all [row][j])
__device__ float g_slin[JD];

// ---- packed fp32x2 helpers ------------------------------------------------
__device__ __forceinline__ u64 pk2(float a, float b) {
    u64 r;
    asm("mov.b64 %0, {%1, %2};" : "=l"(r) : "r"(__float_as_uint(a)), "r"(__float_as_uint(b)));
    return r;
}
__device__ __forceinline__ float2 upk(u64 v) {
    unsigned lo, hi;
    asm("mov.b64 {%0, %1}, %2;" : "=r"(lo), "=r"(hi) : "l"(v));
    return make_float2(__uint_as_float(lo), __uint_as_float(hi));
}
__device__ __forceinline__ void fma2(u64& d, u64 a, u64 b) {
    asm("fma.rn.f32x2 %0, %1, %2, %0;" : "+l"(d) : "l"(a), "l"(b));
}
__device__ __forceinline__ void add2(u64& d, u64 a) {
    asm("add.rn.f32x2 %0, %0, %1;" : "+l"(d) : "l"(a));
}
// vectored global float reduction (sm_90+), 4 floats per op
__device__ __forceinline__ void red4(float* gp, float a, float b, float c, float d) {
    asm volatile(
        "{\n\t.reg .u64 p;\n\t"
        "cvta.to.global.u64 p, %0;\n\t"
        "red.global.add.v4.f32 [p], {%1, %2, %3, %4};\n\t}"
        :: "l"(gp), "f"(a), "f"(b), "f"(c), "f"(d) : "memory");
}
// ---- cp.async helpers -------------------------------------------------------
__device__ __forceinline__ unsigned sptr(const void* p) {
    return (unsigned)__cvta_generic_to_shared(p);
}
__device__ __forceinline__ void cp16(unsigned smem_dst, const void* gmem_src) {
    asm volatile("cp.async.cg.shared.global [%0], [%1], 16;"
                 :: "r"(smem_dst), "l"(gmem_src));
}
__device__ __forceinline__ void cp_commit() {
    asm volatile("cp.async.commit_group;");
}
template<int N>
__device__ __forceinline__ void cp_wait() {
    asm volatile("cp.async.wait_group %0;" :: "n"(N));
}

// --------------------------------------------------------------------------
// smem layouts
// --------------------------------------------------------------------------
struct RGSmem {                             // 28672 B
    ulonglong2 ss[2][JD][CPK / 4];          // 2 x 6KB   S-tile double buffer
    float buf[2][RGROWS][CPK];              // 2 x 8KB   stream double buffer
};
struct SKSmem {                             // 34304 B
    float ws[JD][64];                       // factor (RPS <= 64)
    float buf[8][1024];                     // 8-stage stream ring
};
#define PH1_SMEM 34816

// --------------------------------------------------------------------------
__device__ __forceinline__ void slin_body(const float* __restrict__ Wlin) {
    const int wid = threadIdx.x >> 5;
    const int lane = threadIdx.x & 31;
    if (wid < JD) {
        const float4* p = (const float4*)(Wlin + wid * N_DIM);
        float s = 0.0f;
        for (int q = lane; q < N_DIM / 4; q += 32) {
            float4 v = p[q];
            s += v.x + v.y + v.z + v.w;
        }
        #pragma unroll
        for (int o = 16; o; o >>= 1) s += __shfl_xor_sync(0xffffffffu, s, o);
        if (lane == 0) g_slin[wid] = s;
    }
}

// split-K accumulation: RPS_ rows x 1024 cols, 8-stage per-thread cp.async ring
// (thread consumes exactly the bytes it copied -> no barriers in the loop).
template<int RPS_>
__device__ __forceinline__ void splitk_accum(const float* __restrict__ big,
                                             float* __restrict__ out,
                                             int cslab, int r0,
                                             const float (*ws)[64],
                                             float* __restrict__ buf) {
    const int tid = threadIdx.x;
    const int c0 = cslab * 1024 + tid * 4;
    const float* gp = big + (size_t)r0 * N_DIM + c0;
    const unsigned sb = sptr(buf) + tid * 16;

    #pragma unroll
    for (int s = 0; s < 7; s++) {           // 7 stages in flight
        cp16(sb + s * 4096, gp + (size_t)s * N_DIM);
        cp_commit();
    }

    u64 acc[JD][2];
    #pragma unroll
    for (int j = 0; j < JD; j++) { acc[j][0] = 0ull; acc[j][1] = 0ull; }

    #pragma unroll 4
    for (int rr = 0; rr < RPS_; rr++) {
        const int nxt = rr + 7;
        if (nxt < RPS_) cp16(sb + (nxt & 7) * 4096, gp + (size_t)nxt * N_DIM);
        cp_commit();
        cp_wait<7>();                       // stage rr complete
        ulonglong2 d = *(const ulonglong2*)(buf + (rr & 7) * 1024 + tid * 4);
        #pragma unroll
        for (int j = 0; j < JD; j++) {
            u64 wp = pk2(ws[j][rr], ws[j][rr]);
            fma2(acc[j][0], d.x, wp);
            fma2(acc[j][1], d.y, wp);
        }
    }

    #pragma unroll
    for (int j = 0; j < JD; j++) {
        float2 a = upk(acc[j][0]), b = upk(acc[j][1]);
        red4(out + j * N_DIM + c0, a.x, a.y, b.x, b.y);
    }
}

template<int RPS_>
__device__ __forceinline__ void splitk_body(const float* __restrict__ big,
                                            const float* __restrict__ w,
                                            float* __restrict__ out,
                                            int cslab, int split,
                                            SKSmem* sm) {
    const int tid = threadIdx.x;
    const int r0 = split * RPS_;
    for (int idx = tid; idx < JD * RPS_; idx += NTHR) {
        int j = idx / RPS_, rr = idx % RPS_;
        sm->ws[j][rr] = w[j * N_DIM + r0 + rr];
    }
    __syncthreads();
    splitk_accum<RPS_>(big, out, cslab, r0,
                       (const float (*)[64])sm->ws, &sm->buf[0][0]);
}

// --------------------------------------------------------------------------
// rowgemv3: block = 8 rows (one per warp), loop over 16 column chunks with
// double-buffered cp.async prefetch. Accumulators persist across chunks;
// final values written directly (no partial slabs).
// --------------------------------------------------------------------------
__device__ __forceinline__ void rg3_prefetch(const float* __restrict__ S,
                                             const float* __restrict__ grow,
                                             RGSmem* sm, int b, int cbase,
                                             int tid, int wid, int lane) {
    for (int idx = tid; idx < JD * (CPK / 4); idx += NTHR)
        cp16(sptr(&sm->ss[b][idx >> 6][idx & 63]),
             (const char*)(S + (idx >> 6) * N_DIM + cbase) + (idx & 63) * 16);
    #pragma unroll
    for (int it = 0; it < CPK / 128; it++) {     // 2
        const int q = it * 32 + lane;
        cp16(sptr(&sm->buf[b][wid][q * 4]), grow + cbase + q * 4);
    }
}

__device__ __forceinline__ void rowgemv3_body(const float* __restrict__ big,
                                              const float* __restrict__ S,
                                              float* __restrict__ fin,
                                              int rowblk, RGSmem* sm) {
    const int tid = threadIdx.x;
    const int wid = tid >> 5;
    const int lane = tid & 31;
    const int r = rowblk * RGROWS + wid;
    const float* grow = big + (size_t)r * N_DIM;

    rg3_prefetch(S, grow, sm, 0, 0, tid, wid, lane);
    cp_commit();

    u64 acc[JD];
    #pragma unroll
    for (int j = 0; j < JD; j++) acc[j] = 0ull;

    for (int ks = 0; ks < KS_ITERS; ks++) {
        const int b = ks & 1;
        __syncthreads();                    // readers of buffer b^1 done
        if (ks + 1 < KS_ITERS) {
            rg3_prefetch(S, grow, sm, b ^ 1, (ks + 1) * CPK, tid, wid, lane);
            cp_commit();
            cp_wait<1>();                   // chunk ks complete, ks+1 in flight
        } else {
            cp_wait<0>();
        }
        __syncthreads();                    // buffer b visible to all

        #pragma unroll
        for (int it = 0; it < CPK / 128; it++) {
            const int q = it * 32 + lane;
            ulonglong2 m = *(const ulonglong2*)&sm->buf[b][wid][q * 4];
            #pragma unroll
            for (int j = 0; j < JD; j++) {
                ulonglong2 sv = sm->ss[b][j][q];
                fma2(acc[j], m.x, sv.x);
                fma2(acc[j], m.y, sv.y);
            }
        }
    }

    #pragma unroll
    for (int j = 0; j < JD; j++) {
        #pragma unroll
        for (int o = 16; o; o >>= 1)
            add2(acc[j], __shfl_xor_sync(0xffffffffu, acc[j], o));
    }
    if (lane == 0) {
        #pragma unroll
        for (int j = 0; j < JD; j++) {
            float2 f = upk(acc[j]);
            fin[(size_t)r * JD + j] = f.x + f.y;
        }
    }
}

// --------------------------------------------------------------------------
// Phase 1: T-splitk (red.v4 into g_T) + k-rowgemv3 (g_fin0) + slin.
// --------------------------------------------------------------------------
__global__ void __launch_bounds__(NTHR) phase1_kernel(
        const float* __restrict__ data_q, const float* __restrict__ W_lin,
        const float* __restrict__ W_k,    const float* __restrict__ data_k) {
    __shared__ __align__(16) char smem[PH1_SMEM];
    const int bid = blockIdx.x;
    if (bid < SPLITK_T_BLOCKS) {
        splitk_body<RPS_T>(data_q, W_lin, g_T, bid & 3, bid >> 2, (SKSmem*)smem);
    } else if (bid < SPLITK_T_BLOCKS + RGX) {
        rowgemv3_body(W_k, data_k, g_fin[0], bid - SPLITK_T_BLOCKS, (RGSmem*)smem);
    } else {
        slin_body(W_lin);
    }
}

// nq pass: W_q x g_T -> g_fin1
__global__ void __launch_bounds__(NTHR) nq_kernel(const float* __restrict__ W_q) {
    __shared__ __align__(16) RGSmem sm;
    rowgemv3_body(W_q, g_T, g_fin[1], blockIdx.x, &sm);
}

// v pass: prologue computes kmod for this block's 32 rows from k/nq finals,
// then 8-stage-ring splitk over W_q into g_v. cslab 0 persists g_kmod.
__global__ void __launch_bounds__(NTHR) vsplit_kernel(
        const float* __restrict__ W_q, const float* __restrict__ b_k,
        const float* __restrict__ b_q, const float* __restrict__ b_lin) {
    __shared__ __align__(16) SKSmem sm;
    const int tid = threadIdx.x;
    const int cslab = blockIdx.x;
    const int r0 = blockIdx.y * RPS_V;

    if (tid < JD * RPS_V) {                    // 192 threads
        const int rr = tid & 31;
        const int j = tid >> 5;
        const int m = r0 + rr;
        float kv = g_fin[0][(size_t)m * JD + j] + b_k[m];
        float nqv = g_fin[1][(size_t)m * JD + j] + b_q[m] * g_slin[j] + b_lin[j];
        float x = fmaf(kv, kv, 2.0f * kv) + nqv * (1.0f + fabsf(kv));
        float km = fminf(fmaxf(x, 0.0f), 6.0f);
        sm.ws[j][rr] = km;
        if (cslab == 0) g_kmod[j * N_DIM + m] = km;
    }
    __syncthreads();

    splitk_accum<RPS_V>(W_q, g_v, cslab, r0,
                        (const float (*)[64])sm.ws, &sm.buf[0][0]);
}

// dot pass: data_q x g_v -> g_fin2
__global__ void __launch_bounds__(NTHR) dot_kernel(const float* __restrict__ data_q) {
    __shared__ __align__(16) RGSmem sm;
    rowgemv3_body(data_q, g_v, g_fin[2], blockIdx.x, &sm);
}

// --------------------------------------------------------------------------
// Epilogue B: per-block compute c[j] = sum_m b_q[m]*kmod[j,m] (redundant x32),
// then out[m,j] = (dotfin[m][j] + c[j]) / 64.
// Tail: re-zero g_T and g_v for the next call (graph replays).
// --------------------------------------------------------------------------
__global__ void __launch_bounds__(128) epilogueB_kernel(
        const float* __restrict__ b_q, float* __restrict__ out) {
    __shared__ float red[JD][128];
    __shared__ float cs[JD];
    const int tid = threadIdx.x;

    float cl[JD];
    #pragma unroll
    for (int j = 0; j < JD; j++) cl[j] = 0.f;
    #pragma unroll 4
    for (int i = 0; i < 32; i++) {
        const int m = i * 128 + tid;
        const float b = b_q[m];
        #pragma unroll
        for (int j = 0; j < JD; j++) cl[j] = fmaf(b, g_kmod[j * N_DIM + m], cl[j]);
    }
    #pragma unroll
    for (int j = 0; j < JD; j++) red[j][tid] = cl[j];
    __syncthreads();
    for (int s = 64; s > 0; s >>= 1) {
        if (tid < s) {
            #pragma unroll
            for (int j = 0; j < JD; j++) red[j][tid] += red[j][tid + s];
        }
        __syncthreads();
    }
    if (tid < JD) cs[tid] = red[tid][0];
    __syncthreads();

    const int m = blockIdx.x * 128 + tid;
    #pragma unroll
    for (int j = 0; j < JD; j++)
        out[m * JD + j] = (g_fin[2][(size_t)m * JD + j] + cs[j]) * 0.015625f;

    // tail-zero accumulators for the next invocation
    const int gt = blockIdx.x * 128 + tid;               // 4096 threads
    float4* t4 = (float4*)g_T;
    float4* v4 = (float4*)g_v;
    const float4 z = make_float4(0.f, 0.f, 0.f, 0.f);
    #pragma unroll
    for (int idx = gt; idx < JD * N_DIM / 4; idx += EPIB_BLOCKS * 128) {
        t4[idx] = z;
        v4[idx] = z;
    }
}

// --------------------------------------------------------------------------
extern "C" void kernel_launch(void* const* d_in, const int* in_sizes, int n_in,
                              void* d_out, int out_size) {
    const float* data_q = (const float*)d_in[0];   // [4096,4096]
    const float* data_k = (const float*)d_in[1];   // [6,4096]
    const float* W_q    = (const float*)d_in[2];   // [4096,4096]
    const float* b_q    = (const float*)d_in[3];   // [4096]
    const float* W_lin  = (const float*)d_in[4];   // [6,4096]
    const float* b_lin  = (const float*)d_in[5];   // [6]
    const float* W_k    = (const float*)d_in[6];   // [4096,4096]
    const float* b_k    = (const float*)d_in[7];   // [4096]
    float* out = (float*)d_out;                    // [4096,6]

    phase1_kernel<<<SPLITK_T_BLOCKS + RGX + 1, NTHR>>>(data_q, W_lin, W_k, data_k);
    nq_kernel<<<RGX, NTHR>>>(W_q);                                     // nq finals
    vsplit_kernel<<<dim3(4, NSPLIT_V), NTHR>>>(W_q, b_k, b_q, b_lin);  // kmod + v
    dot_kernel<<<RGX, NTHR>>>(data_q);                                 // dot finals
    epilogueB_kernel<<<EPIB_BLOCKS, 128>>>(b_q, out);                  // c + out + re-zero
}